// round 1
// baseline (speedup 1.0000x reference)
#include <cuda_runtime.h>

// rate_loss: x (32,64,128,128) fp32 -> scalar f32
//
// Pipeline (all graph-capturable, no allocs):
//  k_clear : zero global histogram + sum accumulator
//  k_hist  : one pass over x; absolute-keyed histogram k = floor(5x) into 1024 bins
//            (per-warp smem sub-histograms, merged, then global atomics)
//  k_prep  : 1 block; derive vmin from lowest nonzero key, shift into 200 bins,
//            cumsum -> hist_add (window sum) -> g (slope); store float2 table
//  k_loss  : one pass over x; i = clip(floor((x - vmin - .5)*5),0,194);
//            nloss = (x-left)*g[i] + hist_add[i] + 1e-8; acc += log2(nloss)
//  k_final : out = -sum / n   (== sum(log(nloss)) / (-ln2) / n)

#define NBINS_MAX 200
#define BPU_I     5
#define GLEN      195   // NBINS_MAX - BPU
#define HLEN      196   // NBINS_MAX - BPU + 1
#define KBINS     1024  // wide absolute-key histogram
#define KOFF      512
#define HCOPIES   8     // one per warp (256 threads / 32)
#define HSTRIDE   1028  // 1024 + 4 -> rotate banks per warp

__device__ unsigned int d_hist[KBINS];
__device__ double       d_sum;
__device__ float2       d_gh[GLEN];     // {g[i], hist_add[i]}
__device__ float        d_vminnew;

// ---------------------------------------------------------------- clear
__global__ void k_clear() {
    int t = blockIdx.x * blockDim.x + threadIdx.x;
    if (t < KBINS) d_hist[t] = 0u;
    if (t == 0) d_sum = 0.0;
}

// ---------------------------------------------------------------- histogram
__global__ void __launch_bounds__(256) k_hist(const float* __restrict__ x,
                                              int n4, int n) {
    __shared__ unsigned int sh[HCOPIES * HSTRIDE];
    for (int i = threadIdx.x; i < HCOPIES * HSTRIDE; i += 256) sh[i] = 0u;
    __syncthreads();

    unsigned int* h = sh + (threadIdx.x >> 5) * HSTRIDE;
    const float4* x4 = (const float4*)x;
    int stride = gridDim.x * 256;

    for (int idx = blockIdx.x * 256 + threadIdx.x; idx < n4; idx += stride) {
        float4 v = __ldg(&x4[idx]);
        int k0 = __float2int_rd(v.x * 5.0f);
        int k1 = __float2int_rd(v.y * 5.0f);
        int k2 = __float2int_rd(v.z * 5.0f);
        int k3 = __float2int_rd(v.w * 5.0f);
        k0 = min(KBINS - 1 - KOFF, max(-KOFF, k0));
        k1 = min(KBINS - 1 - KOFF, max(-KOFF, k1));
        k2 = min(KBINS - 1 - KOFF, max(-KOFF, k2));
        k3 = min(KBINS - 1 - KOFF, max(-KOFF, k3));
        atomicAdd(&h[k0 + KOFF], 1u);
        atomicAdd(&h[k1 + KOFF], 1u);
        atomicAdd(&h[k2 + KOFF], 1u);
        atomicAdd(&h[k3 + KOFF], 1u);
    }
    // scalar tail (n not multiple of 4)
    for (int idx = n4 * 4 + blockIdx.x * 256 + threadIdx.x; idx < n; idx += stride) {
        int k = __float2int_rd(__ldg(&x[idx]) * 5.0f);
        k = min(KBINS - 1 - KOFF, max(-KOFF, k));
        atomicAdd(&h[k + KOFF], 1u);
    }
    __syncthreads();

    for (int b = threadIdx.x; b < KBINS; b += 256) {
        unsigned int s = 0;
        #pragma unroll
        for (int c = 0; c < HCOPIES; c++) s += sh[c * HSTRIDE + b];
        if (s) atomicAdd(&d_hist[b], s);
    }
}

// ---------------------------------------------------------------- prep (tiny)
__global__ void __launch_bounds__(256) k_prep(int n) {
    __shared__ unsigned int hist[KBINS];
    __shared__ int kmin_sh;
    if (threadIdx.x == 0) kmin_sh = KBINS;
    for (int b = threadIdx.x; b < KBINS; b += 256) hist[b] = d_hist[b];
    __syncthreads();
    for (int b = threadIdx.x; b < KBINS; b += 256)
        if (hist[b]) atomicMin(&kmin_sh, b);
    __syncthreads();

    if (threadIdx.x == 0) {
        int kmin = kmin_sh - KOFF;                       // lowest key floor(5x)
        // floor(min) = floorDiv(kmin, 5)  (exact: see header derivation)
        int jmin = (kmin >= 0) ? (kmin / 5) : -((-kmin + 4) / 5);
        int vmin_i = jmin - 1;                            // vmin (integer)
        int shift = 5 * vmin_i;                           // hidx = k - 5*vmin

        float cnt[NBINS_MAX];
        for (int i = 0; i < NBINS_MAX; i++) cnt[i] = 0.0f;
        for (int b = 0; b < KBINS; b++) {
            unsigned int c = hist[b];
            if (!c) continue;
            int t = (b - KOFF) - shift;
            t = min(NBINS_MAX - 1, max(0, t));
            cnt[t] += (float)c;
        }
        float inv_n = 1.0f / (float)n;
        // cumsum in fp32 (matches reference jnp fp32 path closely enough)
        float c_arr[NBINS_MAX + 1];
        c_arr[0] = 0.0f;
        for (int i = 0; i < NBINS_MAX; i++)
            c_arr[i + 1] = c_arr[i] + cnt[i] * inv_n;
        float hist_add[HLEN];
        for (int i = 0; i < HLEN; i++)
            hist_add[i] = c_arr[i + BPU_I] - c_arr[i];
        for (int i = 0; i < GLEN; i++) {
            float g = (hist_add[i + 1] - hist_add[i]) * 5.0f;
            d_gh[i] = make_float2(g, hist_add[i]);
        }
        d_vminnew = (float)vmin_i + 0.5f;
    }
}

// ---------------------------------------------------------------- loss
__device__ __forceinline__ float eval_one(float xv, float vmn, const float2* gh) {
    float t = (xv - vmn) * 5.0f;
    float f = floorf(t);
    f = fminf(fmaxf(f, 0.0f), (float)(GLEN - 1));
    int i = (int)f;
    float left = fmaf(f, 0.2f, vmn);
    float2 p = gh[i];
    float nl = fmaf(xv - left, p.x, p.y) + 1e-8f;
    return __log2f(nl);
}

__global__ void __launch_bounds__(256) k_loss(const float* __restrict__ x,
                                              int n4, int n) {
    __shared__ float2 gh[GLEN];
    __shared__ float wsum[8];
    for (int i = threadIdx.x; i < GLEN; i += 256) gh[i] = d_gh[i];
    float vmn = d_vminnew;
    __syncthreads();

    const float4* x4 = (const float4*)x;
    int stride = gridDim.x * 256;
    float acc = 0.0f;

    for (int idx = blockIdx.x * 256 + threadIdx.x; idx < n4; idx += stride) {
        float4 v = __ldg(&x4[idx]);
        acc += eval_one(v.x, vmn, gh);
        acc += eval_one(v.y, vmn, gh);
        acc += eval_one(v.z, vmn, gh);
        acc += eval_one(v.w, vmn, gh);
    }
    for (int idx = n4 * 4 + blockIdx.x * 256 + threadIdx.x; idx < n; idx += stride)
        acc += eval_one(__ldg(&x[idx]), vmn, gh);

    // block reduce (fp32 within warp, fp64 across blocks)
    #pragma unroll
    for (int o = 16; o > 0; o >>= 1)
        acc += __shfl_down_sync(0xffffffffu, acc, o);
    int wid = threadIdx.x >> 5, lid = threadIdx.x & 31;
    if (lid == 0) wsum[wid] = acc;
    __syncthreads();
    if (wid == 0) {
        float s = (lid < 8) ? wsum[lid] : 0.0f;
        #pragma unroll
        for (int o = 4; o > 0; o >>= 1)
            s += __shfl_down_sync(0xffffffffu, s, o);
        if (lid == 0) atomicAdd(&d_sum, (double)s);
    }
}

// ---------------------------------------------------------------- finalize
__global__ void k_final(float* __restrict__ out, int n) {
    // sum(log(nloss)) / (-ln2) / n  ==  -sum(log2(nloss)) / n
    out[0] = (float)(-d_sum / (double)n);
}

// ---------------------------------------------------------------- launch
extern "C" void kernel_launch(void* const* d_in, const int* in_sizes, int n_in,
                              void* d_out, int out_size) {
    const float* x = (const float*)d_in[0];
    int n  = in_sizes[0];
    int n4 = n >> 2;
    const int GRID = 1184;  // 8 per SM * 148

    k_clear<<<4, 256>>>();
    k_hist<<<GRID, 256>>>(x, n4, n);
    k_prep<<<1, 256>>>(n);
    k_loss<<<GRID, 256>>>(x, n4, n);
    k_final<<<1, 1>>>((float*)d_out, n);
}